// round 8
// baseline (speedup 1.0000x reference)
#include <cuda_runtime.h>
#include <cuda_bf16.h>
#include <cstdint>

#define BATCH 16
#define NQ 2048
#define NK 2048
#define DHEAD 128
#define KBLOCKS 16
#define INV_SQRT_SCALE 0.08838834764831845f  // 1/sqrt(128)

// ---------------------------------------------------------------------------
// Global scratch: pre-split bf16 hi/lo copies of q, k, v.
// ---------------------------------------------------------------------------
#define TENSOR_ELEMS ((size_t)BATCH * NQ * DHEAD)
__device__ __align__(16) __nv_bfloat16 g_qh[TENSOR_ELEMS];
__device__ __align__(16) __nv_bfloat16 g_ql[TENSOR_ELEMS];
__device__ __align__(16) __nv_bfloat16 g_kh[TENSOR_ELEMS];
__device__ __align__(16) __nv_bfloat16 g_kl[TENSOR_ELEMS];
__device__ __align__(16) __nv_bfloat16 g_vh[TENSOR_ELEMS];
__device__ __align__(16) __nv_bfloat16 g_vl[TENSOR_ELEMS];
__device__ float g_partial[(size_t)BATCH * NQ * KBLOCKS];
__device__ int g_mask_mode;   // 0 = bytes, 1 = int32, 2 = float32

// ---------------------------------------------------------------------------
// K1 smem: 2 bufs x 4 tensors (Qh,Ql,Kh,Kl), each 128 rows x 32 bf16, row
// stride 80 B. Row-sum partial array (128 x 4 f32) overlays the buffers.
// ---------------------------------------------------------------------------
#define K1_CH 10240                        // 128 * 80
#define K1_BUF(b) ((b) * 4 * K1_CH)        // 40960 per buf
#define SMEM_K1 81920
#define SCSTRIDE 132

// ---------------------------------------------------------------------------
// K2 smem: att fp32 chunk (128 x 32, stride 144 B) x2 bufs; V chunk (32 x 128
// bf16 h+l, stride 272 B) x2 bufs; E (128 x 32 bf16 h+l, row stride 80 B)
// single; rd[128]. Ctx staging overlays [0, 67584).
// ---------------------------------------------------------------------------
#define K2_ATT(b) ((b) * 18432)            // 128*144
#define K2_OFF_V 36864
#define K2_V(b) (K2_OFF_V + (b) * 17408)   // vh 8704 + vl 8704
#define K2_OFF_E 71680                     // Eh 10240, El 10240
#define K2_ESTRIDE 80
#define K2_EL 10240
#define K2_OFF_RD 92160
#define SMEM_K2 92672

// ---------------------------------------------------------------------------
// PTX primitives (portable, base sm_103 target)
// ---------------------------------------------------------------------------
__device__ __forceinline__ uint32_t smem_u32(const void* p) {
    uint32_t a;
    asm("{ .reg .u64 t; cvta.to.shared.u64 t, %1; cvt.u32.u64 %0, t; }" : "=r"(a) : "l"(p));
    return a;
}
__device__ __forceinline__ void ldsm_x4(uint32_t a, uint32_t r[4]) {
    asm volatile("ldmatrix.sync.aligned.m8n8.x4.shared.b16 {%0,%1,%2,%3}, [%4];"
        : "=r"(r[0]), "=r"(r[1]), "=r"(r[2]), "=r"(r[3]) : "r"(a));
}
__device__ __forceinline__ void ldsm_x2(uint32_t a, uint32_t r[2]) {
    asm volatile("ldmatrix.sync.aligned.m8n8.x2.shared.b16 {%0,%1}, [%2];"
        : "=r"(r[0]), "=r"(r[1]) : "r"(a));
}
__device__ __forceinline__ void ldsm_x4t(uint32_t a, uint32_t r[4]) {
    asm volatile("ldmatrix.sync.aligned.m8n8.x4.trans.shared.b16 {%0,%1,%2,%3}, [%4];"
        : "=r"(r[0]), "=r"(r[1]), "=r"(r[2]), "=r"(r[3]) : "r"(a));
}
__device__ __forceinline__ void mma16816(float c[4], const uint32_t a[4], uint32_t b0, uint32_t b1) {
    asm volatile("mma.sync.aligned.m16n8k16.row.col.f32.bf16.bf16.f32 "
        "{%0,%1,%2,%3}, {%4,%5,%6,%7}, {%8,%9}, {%0,%1,%2,%3};"
        : "+f"(c[0]), "+f"(c[1]), "+f"(c[2]), "+f"(c[3])
        : "r"(a[0]), "r"(a[1]), "r"(a[2]), "r"(a[3]), "r"(b0), "r"(b1));
}
__device__ __forceinline__ void cp16(uint32_t dst, const void* src) {
    asm volatile("cp.async.cg.shared.global [%0], [%1], 16;" :: "r"(dst), "l"(src));
}
#define CP_COMMIT() asm volatile("cp.async.commit_group;")
#define CP_WAIT1()  asm volatile("cp.async.wait_group 1;")
#define CP_WAIT0()  asm volatile("cp.async.wait_group 0;")

__device__ __forceinline__ uint32_t pack2(__nv_bfloat16 a, __nv_bfloat16 b) {
    __nv_bfloat162 t = __halves2bfloat162(a, b);
    return *reinterpret_cast<uint32_t*>(&t);
}
__device__ __forceinline__ void split2(float x, float y, uint32_t& h, uint32_t& l) {
    __nv_bfloat16 hx = __float2bfloat16(x), hy = __float2bfloat16(y);
    __nv_bfloat16 lx = __float2bfloat16(x - __bfloat162float(hx));
    __nv_bfloat16 ly = __float2bfloat16(y - __bfloat162float(hy));
    h = pack2(hx, hy);
    l = pack2(lx, ly);
}

// ---------------------------------------------------------------------------
__global__ void detect_mask_kernel(const unsigned char* __restrict__ m)
{
    const int tid = threadIdx.x;
    int mis = 0, ftail = 0;
    for (int i = tid * 16; i < tid * 16 + 16; i++) {
        const unsigned char b = m[i];
        if (b) {
            const int r = i & 3;
            if (r == 1) mis = 1;
            else if (r == 2) { if (b != 0x80) mis = 1; else ftail = 1; }
            else if (r == 3) { if (b != 0x3F) mis = 1; else ftail = 1; }
        }
    }
    const int anyMis = __syncthreads_or(mis);
    const int anyF   = __syncthreads_or(ftail);
    if (tid == 0) g_mask_mode = anyMis ? 0 : (anyF ? 2 : 1);
}

__global__ __launch_bounds__(256) void prep_kernel(
    const float* __restrict__ q, const float* __restrict__ k, const float* __restrict__ v)
{
    const size_t t = (size_t)blockIdx.x * 256 + threadIdx.x;   // float4 index
    const float* src;
    __nv_bfloat16 *dh, *dl;
    if (blockIdx.y == 0)      { src = q; dh = g_qh; dl = g_ql; }
    else if (blockIdx.y == 1) { src = k; dh = g_kh; dl = g_kl; }
    else                      { src = v; dh = g_vh; dl = g_vl; }
    const float4 x = ((const float4*)src)[t];
    uint32_t h01, l01, h23, l23;
    split2(x.x, x.y, h01, l01);
    split2(x.z, x.w, h23, l23);
    ((uint2*)dh)[t] = make_uint2(h01, h23);
    ((uint2*)dl)[t] = make_uint2(l01, l23);
}

// ---------------------------------------------------------------------------
// K1: E = exp(mask ? -inf : QK^T * inv), unnormalized + partial row sums.
// D streamed in 4 chunks of 32, cp.async double-buffered. Epilogue directly
// from accumulator registers (no smem staging).
// ---------------------------------------------------------------------------
__device__ __forceinline__ void k1_issue(uint32_t sb, int b, int q0, int k0, int ic, int buf, int tid)
{
    const int d0 = ic * 32;
#pragma unroll
    for (int i = 0; i < 8; i++) {
        const int idx = i * 256 + tid;     // 0..2047
        const int t = idx >> 9;            // tensor 0..3
        const int r = (idx >> 2) & 127;
        const int c = idx & 3;
        const __nv_bfloat16* base = (t == 0) ? g_qh : (t == 1) ? g_ql : (t == 2) ? g_kh : g_kl;
        const int row0 = (t < 2) ? q0 : k0;
        cp16(sb + K1_BUF(buf) + t * K1_CH + r * 80 + c * 16,
             base + ((size_t)(b * NQ + row0 + r)) * DHEAD + d0 + c * 8);
    }
}

__global__ __launch_bounds__(256, 2)
void qk_exp_kernel(const void* __restrict__ mask, float* __restrict__ att)
{
    extern __shared__ char smem[];
    const uint32_t sb = smem_u32(smem);
    const int tid = threadIdx.x;
    const int wid = tid >> 5;
    const int lane = tid & 31;
    const int wm = wid & 1;     // 64-row half
    const int wn = wid >> 1;    // 32-col group

    const int b  = blockIdx.z;
    const int q0 = blockIdx.y * 128;
    const int k0 = blockIdx.x * 128;

    k1_issue(sb, b, q0, k0, 0, 0, tid); CP_COMMIT();
    k1_issue(sb, b, q0, k0, 1, 1, tid); CP_COMMIT();

    float acc[4][4][4];
#pragma unroll
    for (int mt = 0; mt < 4; mt++)
#pragma unroll
        for (int nt = 0; nt < 4; nt++)
#pragma unroll
            for (int r = 0; r < 4; r++) acc[mt][nt][r] = 0.0f;

    const int lm = lane & 15, lq = lane >> 4;
    const int bn = lane & 7,  bk = (lane >> 3) & 1;

    for (int ic = 0; ic < 4; ic++) {
        const int buf = ic & 1;
        if (ic < 3) { CP_WAIT1(); } else { CP_WAIT0(); }
        __syncthreads();

        const uint32_t qb = sb + K1_BUF(buf);
        const uint32_t kb = sb + K1_BUF(buf) + 2 * K1_CH;
#pragma unroll
        for (int ks = 0; ks < 2; ks++) {
            uint32_t ah[4][4], al[4][4], bh[4][2], bl[4][2];
#pragma unroll
            for (int mt = 0; mt < 4; mt++) {
                const uint32_t a = qb + (wm * 64 + mt * 16 + lm) * 80 + (ks * 16 + lq * 8) * 2;
                ldsm_x4(a, ah[mt]);
                ldsm_x4(a + K1_CH, al[mt]);
            }
#pragma unroll
            for (int nt = 0; nt < 4; nt++) {
                const uint32_t a = kb + (wn * 32 + nt * 8 + bn) * 80 + (ks * 16 + bk * 8) * 2;
                ldsm_x2(a, bh[nt]);
                ldsm_x2(a + K1_CH, bl[nt]);
            }
            // Term-outermost order: same-acc reuse distance = 16 MMAs.
#pragma unroll
            for (int mt = 0; mt < 4; mt++)
#pragma unroll
                for (int nt = 0; nt < 4; nt++)
                    mma16816(acc[mt][nt], ah[mt], bh[nt][0], bh[nt][1]);
#pragma unroll
            for (int mt = 0; mt < 4; mt++)
#pragma unroll
                for (int nt = 0; nt < 4; nt++)
                    mma16816(acc[mt][nt], ah[mt], bl[nt][0], bl[nt][1]);
#pragma unroll
            for (int mt = 0; mt < 4; mt++)
#pragma unroll
                for (int nt = 0; nt < 4; nt++)
                    mma16816(acc[mt][nt], al[mt], bh[nt][0], bh[nt][1]);
        }
        __syncthreads();
        if (ic + 2 < 4) { k1_issue(sb, b, q0, k0, ic + 2, (ic + 2) & 1, tid); CP_COMMIT(); }
    }

    // ---- Epilogue directly from accumulators ----
    const int mode = g_mask_mode;
    const int r4 = lane >> 2;          // 0..7
    const int c2 = (lane & 3) * 2;     // 0,2,4,6
    float rsum[8];
#pragma unroll
    for (int i = 0; i < 8; i++) rsum[i] = 0.0f;

#pragma unroll
    for (int mt = 0; mt < 4; mt++) {
#pragma unroll
        for (int h = 0; h < 2; h++) {
            const int row = wm * 64 + mt * 16 + h * 8 + r4;
            const size_t rbase = ((size_t)b * NQ + q0 + row) * NK + k0;
#pragma unroll
            for (int nt = 0; nt < 4; nt++) {
                const int col = wn * 32 + nt * 8 + c2;
                const size_t moff = rbase + col;
                bool m0, m1;
                if (mode == 1) {
                    const int2 mm = *(const int2*)((const int*)mask + moff);
                    m0 = mm.x != 0; m1 = mm.y != 0;
                } else if (mode == 0) {
                    const uint16_t mm = *(const uint16_t*)((const unsigned char*)mask + moff);
                    m0 = (mm & 0xffu) != 0u; m1 = (mm >> 8) != 0u;
                } else {
                    const float2 mm = *(const float2*)((const float*)mask + moff);
                    m0 = mm.x != 0.0f; m1 = mm.y != 0.0f;
                }
                const float e0 = m0 ? 0.0f : __expf(acc[mt][nt][h * 2]     * INV_SQRT_SCALE);
                const float e1 = m1 ? 0.0f : __expf(acc[mt][nt][h * 2 + 1] * INV_SQRT_SCALE);
                rsum[mt * 2 + h] += e0 + e1;
                *(float2*)(att + moff) = make_float2(e0, e1);
            }
        }
    }

    // Reduce over the 4 lanes of each column group -> 32-col partials.
#pragma unroll
    for (int i = 0; i < 8; i++) {
        rsum[i] += __shfl_xor_sync(0xffffffffu, rsum[i], 1);
        rsum[i] += __shfl_xor_sync(0xffffffffu, rsum[i], 2);
    }
    __syncthreads();                 // buffers dead; reuse smem for partials
    float* partial = (float*)smem;   // [128][4]
    if ((lane & 3) == 0) {
#pragma unroll
        for (int mt = 0; mt < 4; mt++)
#pragma unroll
            for (int h = 0; h < 2; h++)
                partial[(wm * 64 + mt * 16 + h * 8 + r4) * 4 + wn] = rsum[mt * 2 + h];
    }
    __syncthreads();
    if (tid < 128)
        g_partial[((size_t)b * NQ + q0 + tid) * KBLOCKS + blockIdx.x] =
            (partial[tid * 4] + partial[tid * 4 + 1]) + (partial[tid * 4 + 2] + partial[tid * 4 + 3]);
}

// ---------------------------------------------------------------------------
// K2: normalize att in place; ctx = att @ V. NK streamed in 32-key chunks,
// cp.async double-buffered (att fp32 + pre-split V).
// ---------------------------------------------------------------------------
__device__ __forceinline__ void k2_issue(uint32_t sb, const float* attbase, int b, int ic, int buf, int tid)
{
    const int n0 = ic * 32;
#pragma unroll
    for (int i = 0; i < 8; i++) {
        const int idx = i * 256 + tid;     // 0..2047
        if (idx < 1024) {                  // att fp32 chunk: 128 rows x 8 c16
            const int r = idx >> 3;
            const int c = idx & 7;
            cp16(sb + K2_ATT(buf) + r * 144 + c * 16,
                 attbase + (size_t)r * NK + n0 + c * 4);
        } else {                           // V h/l: 32 rows x 16 c16 each
            const int j = idx - 1024;
            const int h = j >> 9;
            const int r = (j >> 4) & 31;
            const int c = j & 15;
            const __nv_bfloat16* base = h ? g_vl : g_vh;
            cp16(sb + K2_V(buf) + h * 8704 + r * 272 + c * 16,
                 base + ((size_t)(b * NK + n0 + r)) * DHEAD + c * 8);
        }
    }
}

__global__ __launch_bounds__(256, 2)
void av_kernel(float* __restrict__ att, float* __restrict__ ctx)
{
    extern __shared__ char smem[];
    const uint32_t sb = smem_u32(smem);
    float* rd = (float*)(smem + K2_OFF_RD);
    const int tid = threadIdx.x;
    const int wid = tid >> 5;
    const int lane = tid & 31;
    const int wm = wid & 1;
    const int wn = wid >> 1;

    const int b  = blockIdx.y;
    const int q0 = blockIdx.x * 128;

    if (tid < 128) {
        const float* p = &g_partial[((size_t)b * NQ + q0 + tid) * KBLOCKS];
        float s = 0.0f;
#pragma unroll
        for (int i = 0; i < KBLOCKS; i++) s += p[i];
        rd[tid] = 1.0f / s;
    }

    float* attbase = att + ((size_t)b * NQ + q0) * NK;
    k2_issue(sb, attbase, b, 0, 0, tid); CP_COMMIT();
    k2_issue(sb, attbase, b, 1, 1, tid); CP_COMMIT();

    float acc[4][4][4];
#pragma unroll
    for (int mt = 0; mt < 4; mt++)
#pragma unroll
        for (int nt = 0; nt < 4; nt++)
#pragma unroll
            for (int r = 0; r < 4; r++) acc[mt][nt][r] = 0.0f;

    const int lm = lane & 15, lq = lane >> 4;

    for (int ic = 0; ic < NK / 32; ic++) {
        const int buf = ic & 1;
        const int n0 = ic * 32;
        if (ic < NK / 32 - 1) { CP_WAIT1(); } else { CP_WAIT0(); }
        __syncthreads();

        // Normalize att chunk (write back to global) + split into E tiles.
#pragma unroll
        for (int i = 0; i < 4; i++) {
            const int idx = i * 256 + tid;    // 0..1023
            const int r = idx >> 3;
            const int c4 = idx & 7;
            float4 e = *(const float4*)(smem + K2_ATT(buf) + r * 144 + c4 * 16);
            const float rr = rd[r];
            e.x *= rr; e.y *= rr; e.z *= rr; e.w *= rr;
            *(float4*)(attbase + (size_t)r * NK + n0 + c4 * 4) = e;
            uint32_t hh0, ll0, hh1, ll1;
            split2(e.x, e.y, hh0, ll0);
            split2(e.z, e.w, hh1, ll1);
            *(uint2*)(smem + K2_OFF_E + r * K2_ESTRIDE + c4 * 8)          = make_uint2(hh0, hh1);
            *(uint2*)(smem + K2_OFF_E + K2_EL + r * K2_ESTRIDE + c4 * 8)  = make_uint2(ll0, ll1);
        }
        __syncthreads();

        const uint32_t vb = sb + K2_V(buf);
#pragma unroll
        for (int ks = 0; ks < 2; ks++) {
            uint32_t eh[4][4], el[4][4];
#pragma unroll
            for (int mt = 0; mt < 4; mt++) {
                const uint32_t a = sb + K2_OFF_E + (wm * 64 + mt * 16 + lm) * K2_ESTRIDE
                                 + (ks * 16 + lq * 8) * 2;
                ldsm_x4(a, eh[mt]);
                ldsm_x4(a + K2_EL, el[mt]);
            }
#pragma unroll
            for (int ntp = 0; ntp < 2; ntp++) {
                uint32_t vh4[4], vl4[4];
                const uint32_t a = vb + (ks * 16 + lm) * 272 + (wn * 32 + ntp * 16 + lq * 8) * 2;
                ldsm_x4t(a, vh4);
                ldsm_x4t(a + 8704, vl4);
                // Term-outermost order: same-acc reuse distance = 8 MMAs.
#pragma unroll
                for (int mt = 0; mt < 4; mt++) {
                    mma16816(acc[mt][ntp * 2],     eh[mt], vh4[0], vh4[1]);
                    mma16816(acc[mt][ntp * 2 + 1], eh[mt], vh4[2], vh4[3]);
                }
#pragma unroll
                for (int mt = 0; mt < 4; mt++) {
                    mma16816(acc[mt][ntp * 2],     eh[mt], vl4[0], vl4[1]);
                    mma16816(acc[mt][ntp * 2 + 1], eh[mt], vl4[2], vl4[3]);
                }
#pragma unroll
                for (int mt = 0; mt < 4; mt++) {
                    mma16816(acc[mt][ntp * 2],     el[mt], vh4[0], vh4[1]);
                    mma16816(acc[mt][ntp * 2 + 1], el[mt], vh4[2], vh4[3]);
                }
            }
        }
        __syncthreads();
        if (ic + 2 < NK / 32) { k2_issue(sb, attbase, b, ic + 2, (ic + 2) & 1, tid); CP_COMMIT(); }
    }

    // Stage ctx through smem for coalesced writes (overlays buffers).
    float* sc = (float*)smem;
    {
        const int r0 = lane >> 2;
        const int c0 = (lane & 3) * 2;
#pragma unroll
        for (int mt = 0; mt < 4; mt++)
#pragma unroll
            for (int nt = 0; nt < 4; nt++) {
                const int rr = wm * 64 + mt * 16 + r0;
                const int cc = wn * 32 + nt * 8 + c0;
                sc[rr * SCSTRIDE + cc]           = acc[mt][nt][0];
                sc[rr * SCSTRIDE + cc + 1]       = acc[mt][nt][1];
                sc[(rr + 8) * SCSTRIDE + cc]     = acc[mt][nt][2];
                sc[(rr + 8) * SCSTRIDE + cc + 1] = acc[mt][nt][3];
            }
    }
    __syncthreads();
    {
        const int row  = tid & 127;
        const int half = tid >> 7;
        float* o = ctx + ((size_t)b * NQ + q0 + row) * DHEAD + half * 64;
#pragma unroll
        for (int j = 0; j < 16; j++)
            *(float4*)(o + j * 4) = *(const float4*)&sc[row * SCSTRIDE + half * 64 + j * 4];
    }
}

// ---------------------------------------------------------------------------
extern "C" void kernel_launch(void* const* d_in, const int* in_sizes, int n_in,
                              void* d_out, int out_size)
{
    const float* q = (const float*)d_in[0];
    const float* k = (const float*)d_in[1];
    const float* v = (const float*)d_in[2];
    const void*  mask = d_in[3];

    float* out = (float*)d_out;
    float* ctx = out;                                   // [B, NQ, D]
    float* att = out + (size_t)BATCH * NQ * DHEAD;      // [B, NQ, NK]

    cudaFuncSetAttribute(qk_exp_kernel, cudaFuncAttributeMaxDynamicSharedMemorySize, SMEM_K1);
    cudaFuncSetAttribute(av_kernel,     cudaFuncAttributeMaxDynamicSharedMemorySize, SMEM_K2);

    detect_mask_kernel<<<1, 256>>>((const unsigned char*)mask);
    prep_kernel<<<dim3(4096, 3), 256>>>(q, k, v);

    dim3 g1(NK / 128, NQ / 128, BATCH);
    qk_exp_kernel<<<g1, 256, SMEM_K1>>>(mask, att);

    dim3 g2(NQ / 128, BATCH);
    av_kernel<<<g2, 256, SMEM_K2>>>(att, ctx);
}

// round 9
// speedup vs baseline: 1.1408x; 1.1408x over previous
#include <cuda_runtime.h>
#include <cuda_bf16.h>
#include <cstdint>

#define BATCH 16
#define NQ 2048
#define NK 2048
#define DHEAD 128
#define KBLOCKS 16
#define INV_SQRT_SCALE 0.08838834764831845f  // 1/sqrt(128)

// ---------------------------------------------------------------------------
// Global scratch: pre-split bf16 hi/lo copies of q, k, v + bit-packed mask.
// ---------------------------------------------------------------------------
#define TENSOR_ELEMS ((size_t)BATCH * NQ * DHEAD)
__device__ __align__(16) __nv_bfloat16 g_qh[TENSOR_ELEMS];
__device__ __align__(16) __nv_bfloat16 g_ql[TENSOR_ELEMS];
__device__ __align__(16) __nv_bfloat16 g_kh[TENSOR_ELEMS];
__device__ __align__(16) __nv_bfloat16 g_kl[TENSOR_ELEMS];
__device__ __align__(16) __nv_bfloat16 g_vh[TENSOR_ELEMS];
__device__ __align__(16) __nv_bfloat16 g_vl[TENSOR_ELEMS];
__device__ float g_partial[(size_t)BATCH * NQ * KBLOCKS];
__device__ int g_mask_mode;   // 0 = bytes, 1 = int32, 2 = float32
// 1 bit per mask element: word w covers elements [w*32, w*32+32), bit i = elem w*32+i.
#define MBITS_WORDS ((size_t)BATCH * NQ * NK / 32)
__device__ __align__(16) uint32_t g_mbits[MBITS_WORDS];

// ---------------------------------------------------------------------------
// K1 smem: 2 bufs x 4 tensors (Qh,Ql,Kh,Kl), each 128 rows x 32 bf16, row
// stride 80 B. Score staging (128 x 132 f32) overlays the buffers at the end.
// ---------------------------------------------------------------------------
#define K1_CH 10240                        // 128 * 80
#define K1_BUF(b) ((b) * 4 * K1_CH)        // 40960 per buf
#define SMEM_K1 81920
#define SCSTRIDE 132

// ---------------------------------------------------------------------------
// K2 smem: att fp32 chunk (128 x 32, stride 144 B) x2 bufs; V chunk (32 x 128
// bf16 h+l, stride 272 B) x2 bufs; E (128 x 32 bf16 h+l, row stride 80 B)
// single; rd[128]. Ctx staging overlays [0, 67584).
// ---------------------------------------------------------------------------
#define K2_ATT(b) ((b) * 18432)            // 128*144
#define K2_OFF_V 36864
#define K2_V(b) (K2_OFF_V + (b) * 17408)   // vh 8704 + vl 8704
#define K2_OFF_E 71680                     // Eh 10240, El 10240
#define K2_ESTRIDE 80
#define K2_EL 10240
#define K2_OFF_RD 92160
#define SMEM_K2 92672

// ---------------------------------------------------------------------------
// PTX primitives (portable, base sm_103 target)
// ---------------------------------------------------------------------------
__device__ __forceinline__ uint32_t smem_u32(const void* p) {
    uint32_t a;
    asm("{ .reg .u64 t; cvta.to.shared.u64 t, %1; cvt.u32.u64 %0, t; }" : "=r"(a) : "l"(p));
    return a;
}
__device__ __forceinline__ void ldsm_x4(uint32_t a, uint32_t r[4]) {
    asm volatile("ldmatrix.sync.aligned.m8n8.x4.shared.b16 {%0,%1,%2,%3}, [%4];"
        : "=r"(r[0]), "=r"(r[1]), "=r"(r[2]), "=r"(r[3]) : "r"(a));
}
__device__ __forceinline__ void ldsm_x2(uint32_t a, uint32_t r[2]) {
    asm volatile("ldmatrix.sync.aligned.m8n8.x2.shared.b16 {%0,%1}, [%2];"
        : "=r"(r[0]), "=r"(r[1]) : "r"(a));
}
__device__ __forceinline__ void ldsm_x4t(uint32_t a, uint32_t r[4]) {
    asm volatile("ldmatrix.sync.aligned.m8n8.x4.trans.shared.b16 {%0,%1,%2,%3}, [%4];"
        : "=r"(r[0]), "=r"(r[1]), "=r"(r[2]), "=r"(r[3]) : "r"(a));
}
__device__ __forceinline__ void mma16816(float c[4], const uint32_t a[4], uint32_t b0, uint32_t b1) {
    asm volatile("mma.sync.aligned.m16n8k16.row.col.f32.bf16.bf16.f32 "
        "{%0,%1,%2,%3}, {%4,%5,%6,%7}, {%8,%9}, {%0,%1,%2,%3};"
        : "+f"(c[0]), "+f"(c[1]), "+f"(c[2]), "+f"(c[3])
        : "r"(a[0]), "r"(a[1]), "r"(a[2]), "r"(a[3]), "r"(b0), "r"(b1));
}
__device__ __forceinline__ void cp16(uint32_t dst, const void* src) {
    asm volatile("cp.async.cg.shared.global [%0], [%1], 16;" :: "r"(dst), "l"(src));
}
#define CP_COMMIT() asm volatile("cp.async.commit_group;")
#define CP_WAIT1()  asm volatile("cp.async.wait_group 1;")
#define CP_WAIT0()  asm volatile("cp.async.wait_group 0;")

__device__ __forceinline__ uint32_t pack2(__nv_bfloat16 a, __nv_bfloat16 b) {
    __nv_bfloat162 t = __halves2bfloat162(a, b);
    return *reinterpret_cast<uint32_t*>(&t);
}
__device__ __forceinline__ void split2(float x, float y, uint32_t& h, uint32_t& l) {
    __nv_bfloat16 hx = __float2bfloat16(x), hy = __float2bfloat16(y);
    __nv_bfloat16 lx = __float2bfloat16(x - __bfloat162float(hx));
    __nv_bfloat16 ly = __float2bfloat16(y - __bfloat162float(hy));
    h = pack2(hx, hy);
    l = pack2(lx, ly);
}

// ---------------------------------------------------------------------------
__global__ void detect_mask_kernel(const unsigned char* __restrict__ m)
{
    const int tid = threadIdx.x;
    int mis = 0, ftail = 0;
    for (int i = tid * 16; i < tid * 16 + 16; i++) {
        const unsigned char b = m[i];
        if (b) {
            const int r = i & 3;
            if (r == 1) mis = 1;
            else if (r == 2) { if (b != 0x80) mis = 1; else ftail = 1; }
            else if (r == 3) { if (b != 0x3F) mis = 1; else ftail = 1; }
        }
    }
    const int anyMis = __syncthreads_or(mis);
    const int anyF   = __syncthreads_or(ftail);
    if (tid == 0) g_mask_mode = anyMis ? 0 : (anyF ? 2 : 1);
}

// ---------------------------------------------------------------------------
// Bit-pack the mask: 32 elements -> 1 uint32. Pure streaming (268 MB read).
// Works for int32 / float32 (nonzero bit pattern <=> true; -0.0 impossible)
// and raw byte masks.
// ---------------------------------------------------------------------------
__global__ __launch_bounds__(256) void pack_mask_kernel(const void* __restrict__ mask)
{
    const size_t w = (size_t)blockIdx.x * 256 + threadIdx.x;
    const int mode = g_mask_mode;
    uint32_t bits = 0;
    if (mode == 0) {
        const uint4* p = (const uint4*)((const unsigned char*)mask + w * 32);
#pragma unroll
        for (int i = 0; i < 2; i++) {
            const uint4 v = p[i];
            const uint32_t ws[4] = {v.x, v.y, v.z, v.w};
#pragma unroll
            for (int k = 0; k < 4; k++)
#pragma unroll
                for (int byt = 0; byt < 4; byt++)
                    bits |= (uint32_t)(((ws[k] >> (8 * byt)) & 0xffu) != 0u) << (i * 16 + k * 4 + byt);
        }
    } else {
        const uint4* p = (const uint4*)((const uint32_t*)mask + w * 32);
#pragma unroll
        for (int i = 0; i < 8; i++) {
            const uint4 v = p[i];
            bits |= (uint32_t)(v.x != 0u) << (i * 4 + 0);
            bits |= (uint32_t)(v.y != 0u) << (i * 4 + 1);
            bits |= (uint32_t)(v.z != 0u) << (i * 4 + 2);
            bits |= (uint32_t)(v.w != 0u) << (i * 4 + 3);
        }
    }
    g_mbits[w] = bits;
}

__global__ __launch_bounds__(256) void prep_kernel(
    const float* __restrict__ q, const float* __restrict__ k, const float* __restrict__ v)
{
    const size_t t = (size_t)blockIdx.x * 256 + threadIdx.x;   // float4 index
    const float* src;
    __nv_bfloat16 *dh, *dl;
    if (blockIdx.y == 0)      { src = q; dh = g_qh; dl = g_ql; }
    else if (blockIdx.y == 1) { src = k; dh = g_kh; dl = g_kl; }
    else                      { src = v; dh = g_vh; dl = g_vl; }
    const float4 x = ((const float4*)src)[t];
    uint32_t h01, l01, h23, l23;
    split2(x.x, x.y, h01, l01);
    split2(x.z, x.w, h23, l23);
    ((uint2*)dh)[t] = make_uint2(h01, h23);
    ((uint2*)dl)[t] = make_uint2(l01, l23);
}

// ---------------------------------------------------------------------------
// K1: E = exp(mask ? -inf : QK^T * inv), unnormalized + partial row sums.
// D streamed in 4 chunks of 32, cp.async double-buffered. Staged epilogue
// (R7 shape) with bit-packed mask.
// ---------------------------------------------------------------------------
__device__ __forceinline__ void k1_issue(uint32_t sb, int b, int q0, int k0, int ic, int buf, int tid)
{
    const int d0 = ic * 32;
#pragma unroll
    for (int i = 0; i < 8; i++) {
        const int idx = i * 256 + tid;     // 0..2047
        const int t = idx >> 9;            // tensor 0..3
        const int r = (idx >> 2) & 127;
        const int c = idx & 3;
        const __nv_bfloat16* base = (t == 0) ? g_qh : (t == 1) ? g_ql : (t == 2) ? g_kh : g_kl;
        const int row0 = (t < 2) ? q0 : k0;
        cp16(sb + K1_BUF(buf) + t * K1_CH + r * 80 + c * 16,
             base + ((size_t)(b * NQ + row0 + r)) * DHEAD + d0 + c * 8);
    }
}

__global__ __launch_bounds__(256, 2)
void qk_exp_kernel(float* __restrict__ att)
{
    extern __shared__ char smem[];
    const uint32_t sb = smem_u32(smem);
    const int tid = threadIdx.x;
    const int wid = tid >> 5;
    const int lane = tid & 31;
    const int wm = wid & 1;     // 64-row half
    const int wn = wid >> 1;    // 32-col group

    const int b  = blockIdx.z;
    const int q0 = blockIdx.y * 128;
    const int k0 = blockIdx.x * 128;

    k1_issue(sb, b, q0, k0, 0, 0, tid); CP_COMMIT();
    k1_issue(sb, b, q0, k0, 1, 1, tid); CP_COMMIT();

    float acc[4][4][4];
#pragma unroll
    for (int mt = 0; mt < 4; mt++)
#pragma unroll
        for (int nt = 0; nt < 4; nt++)
#pragma unroll
            for (int r = 0; r < 4; r++) acc[mt][nt][r] = 0.0f;

    const int lm = lane & 15, lq = lane >> 4;
    const int bn = lane & 7,  bk = (lane >> 3) & 1;

    for (int ic = 0; ic < 4; ic++) {
        const int buf = ic & 1;
        if (ic < 3) { CP_WAIT1(); } else { CP_WAIT0(); }
        __syncthreads();

        const uint32_t qb = sb + K1_BUF(buf);
        const uint32_t kb = sb + K1_BUF(buf) + 2 * K1_CH;
#pragma unroll
        for (int ks = 0; ks < 2; ks++) {
            uint32_t ah[4][4], al[4][4], bh[4][2], bl[4][2];
#pragma unroll
            for (int mt = 0; mt < 4; mt++) {
                const uint32_t a = qb + (wm * 64 + mt * 16 + lm) * 80 + (ks * 16 + lq * 8) * 2;
                ldsm_x4(a, ah[mt]);
                ldsm_x4(a + K1_CH, al[mt]);
            }
#pragma unroll
            for (int nt = 0; nt < 4; nt++) {
                const uint32_t a = kb + (wn * 32 + nt * 8 + bn) * 80 + (ks * 16 + bk * 8) * 2;
                ldsm_x2(a, bh[nt]);
                ldsm_x2(a + K1_CH, bl[nt]);
            }
#pragma unroll
            for (int mt = 0; mt < 4; mt++)
#pragma unroll
                for (int nt = 0; nt < 4; nt++) {
                    mma16816(acc[mt][nt], ah[mt], bh[nt][0], bh[nt][1]);
                    mma16816(acc[mt][nt], ah[mt], bl[nt][0], bl[nt][1]);
                    mma16816(acc[mt][nt], al[mt], bh[nt][0], bh[nt][1]);
                }
        }
        __syncthreads();
        if (ic + 2 < 4) { k1_issue(sb, b, q0, k0, ic + 2, (ic + 2) & 1, tid); CP_COMMIT(); }
    }

    // Stage scores through smem (overlays buffers; all loads consumed).
    float* sc = (float*)smem;
    {
        const int r0 = lane >> 2;
        const int c0 = (lane & 3) * 2;
#pragma unroll
        for (int mt = 0; mt < 4; mt++)
#pragma unroll
            for (int nt = 0; nt < 4; nt++) {
                const int rr = wm * 64 + mt * 16 + r0;
                const int cc = wn * 32 + nt * 8 + c0;
                sc[rr * SCSTRIDE + cc]           = acc[mt][nt][0];
                sc[rr * SCSTRIDE + cc + 1]       = acc[mt][nt][1];
                sc[(rr + 8) * SCSTRIDE + cc]     = acc[mt][nt][2];
                sc[(rr + 8) * SCSTRIDE + cc + 1] = acc[mt][nt][3];
            }
    }
    __syncthreads();

    {
        const int row  = tid & 127;
        const int half = tid >> 7;
        const size_t roff = ((size_t)b * NQ + q0 + row) * NK + k0 + half * 64;
        // 64 mask bits for this thread's columns: one 8B load.
        const uint2 mb = *(const uint2*)(g_mbits +
            ((size_t)b * NQ + q0 + row) * (NK / 32) + (k0 >> 5) + half * 2);
        float rsum = 0.0f;
#pragma unroll
        for (int j = 0; j < 16; j++) {
            const float4 s4 = *(const float4*)&sc[row * SCSTRIDE + half * 64 + j * 4];
            const uint32_t w = (j < 8) ? mb.x : mb.y;
            const int sh = (j & 7) * 4;
            float e[4];
            const float ss[4] = {s4.x, s4.y, s4.z, s4.w};
#pragma unroll
            for (int jj = 0; jj < 4; jj++)
                e[jj] = ((w >> (sh + jj)) & 1u) ? 0.0f : __expf(ss[jj] * INV_SQRT_SCALE);
            rsum += (e[0] + e[1]) + (e[2] + e[3]);
            *(float4*)(att + roff + j * 4) = make_float4(e[0], e[1], e[2], e[3]);
        }
        sc[row * SCSTRIDE + 128 + half] = rsum;
    }
    __syncthreads();
    if (tid < 128)
        g_partial[((size_t)b * NQ + q0 + tid) * KBLOCKS + blockIdx.x] =
            sc[tid * SCSTRIDE + 128] + sc[tid * SCSTRIDE + 129];
}

// ---------------------------------------------------------------------------
// K2: normalize att in place; ctx = att @ V. NK streamed in 32-key chunks,
// cp.async double-buffered (att fp32 + pre-split V).
// ---------------------------------------------------------------------------
__device__ __forceinline__ void k2_issue(uint32_t sb, const float* attbase, int b, int ic, int buf, int tid)
{
    const int n0 = ic * 32;
#pragma unroll
    for (int i = 0; i < 8; i++) {
        const int idx = i * 256 + tid;     // 0..2047
        if (idx < 1024) {                  // att fp32 chunk: 128 rows x 8 c16
            const int r = idx >> 3;
            const int c = idx & 7;
            cp16(sb + K2_ATT(buf) + r * 144 + c * 16,
                 attbase + (size_t)r * NK + n0 + c * 4);
        } else {                           // V h/l: 32 rows x 16 c16 each
            const int j = idx - 1024;
            const int h = j >> 9;
            const int r = (j >> 4) & 31;
            const int c = j & 15;
            const __nv_bfloat16* base = h ? g_vl : g_vh;
            cp16(sb + K2_V(buf) + h * 8704 + r * 272 + c * 16,
                 base + ((size_t)(b * NK + n0 + r)) * DHEAD + c * 8);
        }
    }
}

__global__ __launch_bounds__(256, 2)
void av_kernel(float* __restrict__ att, float* __restrict__ ctx)
{
    extern __shared__ char smem[];
    const uint32_t sb = smem_u32(smem);
    float* rd = (float*)(smem + K2_OFF_RD);
    const int tid = threadIdx.x;
    const int wid = tid >> 5;
    const int lane = tid & 31;
    const int wm = wid & 1;
    const int wn = wid >> 1;

    const int b  = blockIdx.y;
    const int q0 = blockIdx.x * 128;

    if (tid < 128) {
        const float* p = &g_partial[((size_t)b * NQ + q0 + tid) * KBLOCKS];
        float s = 0.0f;
#pragma unroll
        for (int i = 0; i < KBLOCKS; i++) s += p[i];
        rd[tid] = 1.0f / s;
    }

    float* attbase = att + ((size_t)b * NQ + q0) * NK;
    k2_issue(sb, attbase, b, 0, 0, tid); CP_COMMIT();
    k2_issue(sb, attbase, b, 1, 1, tid); CP_COMMIT();

    float acc[4][4][4];
#pragma unroll
    for (int mt = 0; mt < 4; mt++)
#pragma unroll
        for (int nt = 0; nt < 4; nt++)
#pragma unroll
            for (int r = 0; r < 4; r++) acc[mt][nt][r] = 0.0f;

    const int lm = lane & 15, lq = lane >> 4;

    for (int ic = 0; ic < NK / 32; ic++) {
        const int buf = ic & 1;
        const int n0 = ic * 32;
        if (ic < NK / 32 - 1) { CP_WAIT1(); } else { CP_WAIT0(); }
        __syncthreads();

        // Normalize att chunk (write back to global) + split into E tiles.
#pragma unroll
        for (int i = 0; i < 4; i++) {
            const int idx = i * 256 + tid;    // 0..1023
            const int r = idx >> 3;
            const int c4 = idx & 7;
            float4 e = *(const float4*)(smem + K2_ATT(buf) + r * 144 + c4 * 16);
            const float rr = rd[r];
            e.x *= rr; e.y *= rr; e.z *= rr; e.w *= rr;
            *(float4*)(attbase + (size_t)r * NK + n0 + c4 * 4) = e;
            uint32_t hh0, ll0, hh1, ll1;
            split2(e.x, e.y, hh0, ll0);
            split2(e.z, e.w, hh1, ll1);
            *(uint2*)(smem + K2_OFF_E + r * K2_ESTRIDE + c4 * 8)          = make_uint2(hh0, hh1);
            *(uint2*)(smem + K2_OFF_E + K2_EL + r * K2_ESTRIDE + c4 * 8)  = make_uint2(ll0, ll1);
        }
        __syncthreads();

        const uint32_t vb = sb + K2_V(buf);
#pragma unroll
        for (int ks = 0; ks < 2; ks++) {
            uint32_t eh[4][4], el[4][4];
#pragma unroll
            for (int mt = 0; mt < 4; mt++) {
                const uint32_t a = sb + K2_OFF_E + (wm * 64 + mt * 16 + lm) * K2_ESTRIDE
                                 + (ks * 16 + lq * 8) * 2;
                ldsm_x4(a, eh[mt]);
                ldsm_x4(a + K2_EL, el[mt]);
            }
#pragma unroll
            for (int ntp = 0; ntp < 2; ntp++) {
                uint32_t vh4[4], vl4[4];
                const uint32_t a = vb + (ks * 16 + lm) * 272 + (wn * 32 + ntp * 16 + lq * 8) * 2;
                ldsm_x4t(a, vh4);
                ldsm_x4t(a + 8704, vl4);
#pragma unroll
                for (int mt = 0; mt < 4; mt++) {
                    mma16816(acc[mt][ntp * 2],     eh[mt], vh4[0], vh4[1]);
                    mma16816(acc[mt][ntp * 2 + 1], eh[mt], vh4[2], vh4[3]);
                }
#pragma unroll
                for (int mt = 0; mt < 4; mt++) {
                    mma16816(acc[mt][ntp * 2],     eh[mt], vl4[0], vl4[1]);
                    mma16816(acc[mt][ntp * 2 + 1], eh[mt], vl4[2], vl4[3]);
                }
#pragma unroll
                for (int mt = 0; mt < 4; mt++) {
                    mma16816(acc[mt][ntp * 2],     el[mt], vh4[0], vh4[1]);
                    mma16816(acc[mt][ntp * 2 + 1], el[mt], vh4[2], vh4[3]);
                }
            }
        }
        __syncthreads();
        if (ic + 2 < NK / 32) { k2_issue(sb, attbase, b, ic + 2, (ic + 2) & 1, tid); CP_COMMIT(); }
    }

    // Stage ctx through smem for coalesced writes (overlays buffers).
    float* sc = (float*)smem;
    {
        const int r0 = lane >> 2;
        const int c0 = (lane & 3) * 2;
#pragma unroll
        for (int mt = 0; mt < 4; mt++)
#pragma unroll
            for (int nt = 0; nt < 4; nt++) {
                const int rr = wm * 64 + mt * 16 + r0;
                const int cc = wn * 32 + nt * 8 + c0;
                sc[rr * SCSTRIDE + cc]           = acc[mt][nt][0];
                sc[rr * SCSTRIDE + cc + 1]       = acc[mt][nt][1];
                sc[(rr + 8) * SCSTRIDE + cc]     = acc[mt][nt][2];
                sc[(rr + 8) * SCSTRIDE + cc + 1] = acc[mt][nt][3];
            }
    }
    __syncthreads();
    {
        const int row  = tid & 127;
        const int half = tid >> 7;
        float* o = ctx + ((size_t)b * NQ + q0 + row) * DHEAD + half * 64;
#pragma unroll
        for (int j = 0; j < 16; j++)
            *(float4*)(o + j * 4) = *(const float4*)&sc[row * SCSTRIDE + half * 64 + j * 4];
    }
}

// ---------------------------------------------------------------------------
extern "C" void kernel_launch(void* const* d_in, const int* in_sizes, int n_in,
                              void* d_out, int out_size)
{
    const float* q = (const float*)d_in[0];
    const float* k = (const float*)d_in[1];
    const float* v = (const float*)d_in[2];
    const void*  mask = d_in[3];

    float* out = (float*)d_out;
    float* ctx = out;                                   // [B, NQ, D]
    float* att = out + (size_t)BATCH * NQ * DHEAD;      // [B, NQ, NK]

    cudaFuncSetAttribute(qk_exp_kernel, cudaFuncAttributeMaxDynamicSharedMemorySize, SMEM_K1);
    cudaFuncSetAttribute(av_kernel,     cudaFuncAttributeMaxDynamicSharedMemorySize, SMEM_K2);

    detect_mask_kernel<<<1, 256>>>((const unsigned char*)mask);
    pack_mask_kernel<<<(int)(MBITS_WORDS / 256), 256>>>(mask);
    prep_kernel<<<dim3(4096, 3), 256>>>(q, k, v);

    dim3 g1(NK / 128, NQ / 128, BATCH);
    qk_exp_kernel<<<g1, 256, SMEM_K1>>>(att);

    dim3 g2(NQ / 128, BATCH);
    av_kernel<<<g2, 256, SMEM_K2>>>(att, ctx);
}